// round 14
// baseline (speedup 1.0000x reference)
#include <cuda_runtime.h>
#include <cuda_bf16.h>
#include <cstdint>

#define NN 50000
#define EE 800000
#define HH 128
#define LL 3
#define GG 64
#define BN_EPS 1e-5f
#define SCAN_CH 196

// ---------------- scratch (device globals) ----------------
__device__ __align__(16) float g_y0[NN * HH];
__device__ __align__(16) float g_y1[NN * HH];
__device__ __align__(16) float g_agg[NN * HH];
__device__ __align__(16) __nv_bfloat16 g_Wsw[12 * 8192];  // [split*4+chunk][128n x 64k swizzled]
__device__ __align__(16) float g_bias[HH];
__device__ int   g_rowptr[NN + 1];
__device__ int   g_colidx[EE];
__device__ int   g_cnt[NN];
__device__ float g_invdeg[NN];
__device__ int   g_part[256];
__device__ int   g_base[256];
__device__ __align__(16) float g_sum[2][HH];
__device__ __align__(16) float g_sumsq[2][HH];
__device__ __align__(16) float g_fcs[HH];
__device__ float g_c0;
__device__ float g_pool[GG];

// ---------------- helpers ----------------
__device__ __forceinline__ uint32_t smem_u32(const void* p) {
    uint32_t a;
    asm("{ .reg .u64 t; cvta.to.shared.u64 t, %1; cvt.u32.u64 %0, t; }" : "=r"(a) : "l"(p));
    return a;
}
__device__ __forceinline__ const float* sel_h(const float* x, int s) {
    return (s == 0) ? x : ((s == 1) ? g_y0 : g_y1);
}
__device__ __forceinline__ void get_coef(int layer, const float* gamma, const float* beta,
                                         int c, float& a, float& b) {
    if (layer == 0) { a = 1.f; b = 0.f; return; }
    int p = (layer + 1) & 1;
    float mean = g_sum[p][c] * (1.0f / NN);
    float var  = g_sumsq[p][c] * (1.0f / NN) - mean * mean;
    a = gamma[c] * rsqrtf(var + BN_EPS);
    b = beta[c] - mean * a;
}
// split v0,v1 into 3 bf16x2 words
__device__ __forceinline__ void split3(float v0, float v1,
                                       uint32_t& u1, uint32_t& u2, uint32_t& u3) {
    __nv_bfloat162 b1 = __floats2bfloat162_rn(v0, v1);
    float2 f1 = __bfloat1622float2(b1);
    float r0 = v0 - f1.x, r1 = v1 - f1.y;
    __nv_bfloat162 b2 = __floats2bfloat162_rn(r0, r1);
    float2 f2 = __bfloat1622float2(b2);
    __nv_bfloat162 b3 = __floats2bfloat162_rn(r0 - f2.x, r1 - f2.y);
    u1 = *reinterpret_cast<uint32_t*>(&b1);
    u2 = *reinterpret_cast<uint32_t*>(&b2);
    u3 = *reinterpret_cast<uint32_t*>(&b3);
}

// ---------------- setup kernels ----------------
__global__ void zero_init_kernel() {
    int i = blockIdx.x * blockDim.x + threadIdx.x;
    if (i < NN) g_cnt[i] = 0;
    if (i < GG) g_pool[i] = 0.f;
}
__global__ void count_kernel(const int* __restrict__ dst) {
    int i = blockIdx.x * blockDim.x + threadIdx.x;
    if (i < EE) atomicAdd(&g_cnt[dst[i]], 1);
}
__global__ void scan1_kernel() {
    __shared__ int s[256];
    int b = blockIdx.x, t = threadIdx.x;
    int idx = b * SCAN_CH + t;
    s[t] = (t < SCAN_CH && idx < NN) ? g_cnt[idx] : 0;
    __syncthreads();
    for (int off = 128; off; off >>= 1) {
        if (t < off) s[t] += s[t + off];
        __syncthreads();
    }
    if (t == 0) g_part[b] = s[0];
}
__global__ void scan2_kernel() {
    __shared__ int s[256];
    int t = threadIdx.x;
    s[t] = g_part[t];
    __syncthreads();
    int acc = s[t];
    for (int off = 1; off < 256; off <<= 1) {
        int v = 0;
        if (t >= off) v = s[t - off];
        __syncthreads();
        s[t] += v;
        __syncthreads();
    }
    g_base[t] = s[t] - acc;
}
__global__ void scan3_kernel() {
    __shared__ int s[256];
    int b = blockIdx.x, t = threadIdx.x;
    int idx = b * SCAN_CH + t;
    int c = (t < SCAN_CH && idx < NN) ? g_cnt[idx] : 0;
    s[t] = c;
    __syncthreads();
    int own = s[t];
    for (int off = 1; off < 256; off <<= 1) {
        int v = 0;
        if (t >= off) v = s[t - off];
        __syncthreads();
        s[t] += v;
        __syncthreads();
    }
    if (t < SCAN_CH && idx < NN) {
        g_rowptr[idx] = g_base[b] + s[t] - own;
        g_invdeg[idx] = 1.0f / (float)(c > 1 ? c : 1);
        g_cnt[idx] = 0;
    }
    if (b == 0 && t == 0) g_rowptr[NN] = EE;
}
__global__ void fill_kernel(const int* __restrict__ src, const int* __restrict__ dst) {
    int i = blockIdx.x * blockDim.x + threadIdx.x;
    if (i >= EE) return;
    int d = dst[i];
    int pos = g_rowptr[d] + atomicAdd(&g_cnt[d], 1);
    g_colidx[pos] = src[i];
}

// ---------------- per-layer kernels ----------------
__global__ void agg_kernel(const float* __restrict__ x, int sel, int layer,
                           const float* __restrict__ gammaP,
                           const float* __restrict__ betaP) {
    int t = blockIdx.x * blockDim.x + threadIdx.x;
    int node = t >> 5;
    int lane = t & 31;
    if (node >= NN) return;
    const float4* h4 = (const float4*)sel_h(x, sel);
    float4 acc0 = make_float4(0.f, 0.f, 0.f, 0.f);
    float4 acc1 = make_float4(0.f, 0.f, 0.f, 0.f);
    int e0 = g_rowptr[node];
    int e1 = g_rowptr[node + 1];
    int j = e0;
    for (; j + 1 < e1; j += 2) {
        float4 v0 = h4[g_colidx[j] * 32 + lane];
        float4 v1 = h4[g_colidx[j + 1] * 32 + lane];
        acc0.x += v0.x; acc0.y += v0.y; acc0.z += v0.z; acc0.w += v0.w;
        acc1.x += v1.x; acc1.y += v1.y; acc1.z += v1.z; acc1.w += v1.w;
    }
    if (j < e1) {
        float4 v = h4[g_colidx[j] * 32 + lane];
        acc0.x += v.x; acc0.y += v.y; acc0.z += v.z; acc0.w += v.w;
    }
    acc0.x += acc1.x; acc0.y += acc1.y; acc0.z += acc1.z; acc0.w += acc1.w;
    float4 o = make_float4(0.f, 0.f, 0.f, 0.f);
    if (e1 > e0) {
        float inv = g_invdeg[node];
        float a0, b0, a1, b1, a2, b2, a3, b3;
        get_coef(layer, gammaP, betaP, lane * 4 + 0, a0, b0);
        get_coef(layer, gammaP, betaP, lane * 4 + 1, a1, b1);
        get_coef(layer, gammaP, betaP, lane * 4 + 2, a2, b2);
        get_coef(layer, gammaP, betaP, lane * 4 + 3, a3, b3);
        o = make_float4(fmaf(a0, acc0.x * inv, b0), fmaf(a1, acc0.y * inv, b1),
                        fmaf(a2, acc0.z * inv, b2), fmaf(a3, acc0.w * inv, b3));
    }
    ((float4*)g_agg)[node * 32 + lane] = o;
}

// fold prev affine into weights, 3-way bf16 split, ldmatrix-swizzled [n][k] tiles.
// blocks 0..383: weights. block 384: bias fold + stats zero.
__global__ void prepareW_kernel(const float* __restrict__ wl,
                                const float* __restrict__ wr,
                                const float* __restrict__ bias, int layer,
                                const float* __restrict__ gammaP,
                                const float* __restrict__ betaP) {
    int b = blockIdx.x, tid = threadIdx.x;
    if (b < 384) {
        int idx = b * 256 + tid;          // < 98304
        int s = idx >> 15;                // split
        int rem = idx & 32767;
        int c = rem >> 13;                // k-chunk
        int e = rem & 8191;
        int n = e >> 6;                   // out col 0..127
        int k = e & 63;                   // k in chunk
        int kg = c * 64 + k;
        float v;
        if (kg < HH) {
            v = wl[(layer * HH + n) * HH + kg];
        } else {
            float a, bb;
            get_coef(layer, gammaP, betaP, kg - HH, a, bb);
            v = a * wr[(layer * HH + n) * HH + (kg - HH)];
        }
        __nv_bfloat16 h1 = __float2bfloat16(v);
        float r1 = v - __bfloat162float(h1);
        __nv_bfloat16 h2 = __float2bfloat16(r1);
        float r2 = r1 - __bfloat162float(h2);
        __nv_bfloat16 h3 = __float2bfloat16(r2);
        __nv_bfloat16 hs = (s == 0) ? h1 : ((s == 1) ? h2 : h3);
        uint32_t bo = (uint32_t)(n * 128) + (((uint32_t)(k * 2)) ^ (((uint32_t)n & 7u) << 4));
        g_Wsw[(s * 4 + c) * 8192 + (bo >> 1)] = hs;
    } else {
        __shared__ float cb[HH];
        if (tid < HH) {
            float a, bb;
            get_coef(layer, gammaP, betaP, tid, a, bb);
            cb[tid] = bb;
            g_sum[layer & 1][tid] = 0.f;
            g_sumsq[layer & 1][tid] = 0.f;
        }
        __syncthreads();
        if (tid < HH) {
            float sv = bias[tid];
            const float* w = wr + (layer * HH + tid) * HH;
            for (int k = 0; k < HH; k++) sv += cb[k] * w[k];
            g_bias[tid] = sv;
        }
    }
}

// mma.sync bf16 3-split GEMM: y = relu([agg|h] @ Wfold^T + bias'), fused BN sums.
// 64x128 CTA tile / 4 warps (16 rows each). K=256 in 4 chunks of 64.
__global__ void __launch_bounds__(128, 2)
gemm_kernel(const float* __restrict__ x, int sel, int outsel, int par) {
    __shared__ __align__(16) __nv_bfloat16 sA[3][64 * 64];   // swizzled [row][k], 8KB each
    __shared__ __align__(16) __nv_bfloat16 sW[128 * 64];     // one split, swizzled [n][k], 16KB
    __shared__ float sbias[HH];
    __shared__ float ssum[HH];
    __shared__ float ssq[HH];

    const int tid = threadIdx.x;
    const int warp = tid >> 5;
    const int lane = tid & 31;
    const int row0 = blockIdx.x * 64;

    const float* hin = sel_h(x, sel);
    float* yout = (outsel == 0) ? g_y0 : g_y1;

    if (tid < HH) { sbias[tid] = g_bias[tid]; ssum[tid] = 0.f; ssq[tid] = 0.f; }

    float acc[16][4];
    #pragma unroll
    for (int n = 0; n < 16; n++)
        #pragma unroll
        for (int q = 0; q < 4; q++) acc[n][q] = 0.f;

    const uint32_t sAu = smem_u32(sA);
    const uint32_t sWu = smem_u32(sW);

    // per-thread conversion coords
    const int crow = tid >> 1;          // 0..63
    const int ckh  = tid & 1;           // k half (32 each)
    const int cgrow = row0 + crow;
    const uint32_t csw = ((uint32_t)crow & 7u) << 4;
    const uint32_t crb = (uint32_t)crow * 128u;

    // A-ldmatrix address (per lane), row varies, k varies by ks
    const int lrow = lane & 15;
    const uint32_t lkb = ((uint32_t)(lane >> 4)) << 4;   // +16B for k8-15

    for (int chunk = 0; chunk < 4; chunk++) {
        __syncthreads();   // protect sA/sW from previous iteration readers
        // --- stage A: fp32 -> 3 bf16 splits, swizzled
        {
            const float4* src4 = (const float4*)((chunk < 2) ? g_agg : hin);
            const int base4 = (chunk & 1) * 16 + ckh * 8;
            #pragma unroll
            for (int i = 0; i < 8; i++) {
                float4 q = (cgrow < NN) ? src4[cgrow * 32 + base4 + i]
                                        : make_float4(0.f, 0.f, 0.f, 0.f);
                int kl = ckh * 32 + i * 4;
                uint32_t u1, u2, u3;
                split3(q.x, q.y, u1, u2, u3);
                uint32_t off = crb + (((uint32_t)(kl * 2)) ^ csw);
                *(uint32_t*)((char*)sA[0] + off) = u1;
                *(uint32_t*)((char*)sA[1] + off) = u2;
                *(uint32_t*)((char*)sA[2] + off) = u3;
                split3(q.z, q.w, u1, u2, u3);
                off = crb + (((uint32_t)((kl + 2) * 2)) ^ csw);
                *(uint32_t*)((char*)sA[0] + off) = u1;
                *(uint32_t*)((char*)sA[1] + off) = u2;
                *(uint32_t*)((char*)sA[2] + off) = u3;
            }
        }
        __syncthreads();
        // --- W splits, staged one at a time
        for (int sw = 0; sw < 3; sw++) {
            {
                const uint4* wsrc = (const uint4*)(g_Wsw + (sw * 4 + chunk) * 8192);
                uint4* wdst = (uint4*)sW;
                #pragma unroll
                for (int i = 0; i < 8; i++) wdst[tid + i * 128] = wsrc[tid + i * 128];
            }
            __syncthreads();
            const int npairs = 3 - sw;   // A splits 0..npairs-1 pair with this W split
            #pragma unroll
            for (int ks = 0; ks < 4; ks++) {
                // A fragments for needed splits
                uint32_t af[3][4];
                {
                    uint32_t arow = (uint32_t)(warp * 16 + lrow);
                    uint32_t akb = (uint32_t)(ks * 32) + lkb;
                    uint32_t aoff = arow * 128u + (akb ^ ((arow & 7u) << 4));
                    #pragma unroll
                    for (int p = 0; p < 3; p++) {
                        if (p < npairs) {
                            uint32_t ad = sAu + (uint32_t)p * 8192u + aoff;
                            asm volatile(
                                "ldmatrix.sync.aligned.m8n8.x4.shared.b16 {%0,%1,%2,%3}, [%4];"
                                : "=r"(af[p][0]), "=r"(af[p][1]), "=r"(af[p][2]), "=r"(af[p][3])
                                : "r"(ad));
                        }
                    }
                }
                #pragma unroll
                for (int nt = 0; nt < 16; nt++) {
                    uint32_t bn = (uint32_t)(nt * 8 + (lane & 7));
                    uint32_t bkb = (uint32_t)(ks * 32) + (((uint32_t)(lane >> 3) & 1u) << 4);
                    uint32_t bd = sWu + bn * 128u + (bkb ^ ((bn & 7u) << 4));
                    uint32_t b0, b1;
                    asm volatile(
                        "ldmatrix.sync.aligned.m8n8.x2.shared.b16 {%0,%1}, [%2];"
                        : "=r"(b0), "=r"(b1) : "r"(bd));
                    #pragma unroll
                    for (int p = 0; p < 3; p++) {
                        if (p < npairs) {
                            asm volatile(
                                "mma.sync.aligned.m16n8k16.row.col.f32.bf16.bf16.f32 "
                                "{%0,%1,%2,%3}, {%4,%5,%6,%7}, {%8,%9}, {%0,%1,%2,%3};"
                                : "+f"(acc[nt][0]), "+f"(acc[nt][1]),
                                  "+f"(acc[nt][2]), "+f"(acc[nt][3])
                                : "r"(af[p][0]), "r"(af[p][1]), "r"(af[p][2]), "r"(af[p][3]),
                                  "r"(b0), "r"(b1));
                        }
                    }
                }
            }
            __syncthreads();   // before overwriting sW
        }
    }

    // --- epilogue: bias + relu + BN stats + store
    const int r0 = warp * 16 + (lane >> 2);
    const int r1 = r0 + 8;
    const int g0 = row0 + r0, g1 = row0 + r1;
    const bool v0 = g0 < NN, v1 = g1 < NN;
    #pragma unroll
    for (int nt = 0; nt < 16; nt++) {
        int c = nt * 8 + (lane & 3) * 2;
        float b0 = sbias[c], b1 = sbias[c + 1];
        float e00 = v0 ? fmaxf(acc[nt][0] + b0, 0.f) : 0.f;
        float e01 = v0 ? fmaxf(acc[nt][1] + b1, 0.f) : 0.f;
        float e10 = v1 ? fmaxf(acc[nt][2] + b0, 0.f) : 0.f;
        float e11 = v1 ? fmaxf(acc[nt][3] + b1, 0.f) : 0.f;
        atomicAdd(&ssum[c],     e00 + e10);
        atomicAdd(&ssum[c + 1], e01 + e11);
        atomicAdd(&ssq[c],      e00 * e00 + e10 * e10);
        atomicAdd(&ssq[c + 1],  e01 * e01 + e11 * e11);
        if (v0) *(float2*)(yout + g0 * HH + c) = make_float2(e00, e01);
        if (v1) *(float2*)(yout + g1 * HH + c) = make_float2(e10, e11);
    }
    __syncthreads();
    if (tid < HH) {
        atomicAdd(&g_sum[par][tid],   ssum[tid]);
        atomicAdd(&g_sumsq[par][tid], ssq[tid]);
    }
}

__global__ void fcprep_kernel(const float* __restrict__ fcw,
                              const float* __restrict__ gammaP,
                              const float* __restrict__ betaP) {
    __shared__ float red[128];
    int c = threadIdx.x;
    float w = fcw[c];
    float a, b;
    get_coef(LL, gammaP, betaP, c, a, b);
    g_fcs[c] = a * w;
    red[c] = b * w;
    __syncthreads();
    for (int off = 64; off; off >>= 1) {
        if (c < off) red[c] += red[c + off];
        __syncthreads();
    }
    if (c == 0) g_c0 = red[0];
}

__global__ void pool_kernel(const int* __restrict__ batch) {
    int t = blockIdx.x * blockDim.x + threadIdx.x;
    int node = t >> 5;
    int lane = t & 31;
    if (node >= NN) return;
    float4 v = ((const float4*)g_y0)[node * 32 + lane];
    float4 w = ((const float4*)g_fcs)[lane];
    float s = v.x * w.x + v.y * w.y + v.z * w.z + v.w * w.w;
    #pragma unroll
    for (int off = 16; off; off >>= 1) s += __shfl_down_sync(0xffffffffu, s, off);
    if (lane == 0) atomicAdd(&g_pool[batch[node]], s + g_c0);
}

__global__ void final_kernel(const float* __restrict__ fcb, float* __restrict__ out) {
    int g = threadIdx.x;
    if (g < GG) {
        float z = g_pool[g] + fcb[0];
        out[g] = 1.0f / (1.0f + expf(-z));
    }
}

// ---------------- launch ----------------
extern "C" void kernel_launch(void* const* d_in, const int* in_sizes, int n_in,
                              void* d_out, int out_size) {
    const float* x       = (const float*)d_in[0];
    const int*   ei      = (const int*)d_in[1];
    const int*   src     = ei;
    const int*   dst     = ei + EE;
    const int*   batch   = (const int*)d_in[3];
    const float* lin_l_w = (const float*)d_in[4];
    const float* lin_l_b = (const float*)d_in[5];
    const float* lin_r_w = (const float*)d_in[6];
    const float* gamma   = (const float*)d_in[7];
    const float* beta    = (const float*)d_in[8];
    const float* fcw     = (const float*)d_in[9];
    const float* fcb     = (const float*)d_in[10];
    float*       out     = (float*)d_out;

    zero_init_kernel<<<(NN + 255) / 256, 256>>>();
    count_kernel<<<(EE + 255) / 256, 256>>>(dst);
    scan1_kernel<<<256, 256>>>();
    scan2_kernel<<<1, 256>>>();
    scan3_kernel<<<256, 256>>>();
    fill_kernel<<<(EE + 255) / 256, 256>>>(src, dst);

    for (int l = 0; l < LL; l++) {
        int sel    = (l == 0) ? 0 : ((l == 1) ? 1 : 2);   // x, g_y0, g_y1
        int outsel = (l == 1) ? 1 : 0;                    // y0, y1, y0
        const float* gp = gamma + (l > 0 ? (l - 1) * HH : 0);
        const float* bp = beta  + (l > 0 ? (l - 1) * HH : 0);
        agg_kernel<<<(NN * 32 + 255) / 256, 256>>>(x, sel, l, gp, bp);
        prepareW_kernel<<<385, 256>>>(lin_l_w, lin_r_w, lin_l_b + l * HH, l, gp, bp);
        gemm_kernel<<<(NN + 63) / 64, 128>>>(x, sel, outsel, l & 1);
    }

    fcprep_kernel<<<1, 128>>>(fcw, gamma + 2 * HH, beta + 2 * HH);
    pool_kernel<<<(NN * 32 + 255) / 256, 256>>>(batch);
    final_kernel<<<1, 64>>>(fcb, out);
}